// round 14
// baseline (speedup 1.0000x reference)
#include <cuda_runtime.h>
#include <cuda_fp16.h>
#include <math.h>
#include <stdint.h>

#define BB 256
#define SS 15
#define HH 512
#define VV 50257
#define NBX 393  // (VV + 127) / 128

// Scratch (device globals: no allocation allowed)
__device__ float g_u[BB * HH];
__device__ float g_x[BB * 2 * HH];
__device__ float g_gi[BB * 3 * HH];
__device__ float g_gh[BB * 3 * HH];
__device__ __align__(128) __half g_hnewh[BB * HH];
__device__ float g_pm[BB * NBX];
__device__ float g_ps[BB * NBX];
__device__ float g_lse[BB];

// ---------------------------------------------------------------------------
// helpers
// ---------------------------------------------------------------------------
__device__ __forceinline__ void mma_sync_f16(float* d, const uint32_t* a, const uint32_t* b) {
    asm volatile(
        "mma.sync.aligned.m16n8k16.row.col.f32.f16.f16.f32 "
        "{%0,%1,%2,%3},{%4,%5,%6,%7},{%8,%9},{%0,%1,%2,%3};\n"
        : "+f"(d[0]), "+f"(d[1]), "+f"(d[2]), "+f"(d[3])
        : "r"(a[0]), "r"(a[1]), "r"(a[2]), "r"(a[3]), "r"(b[0]), "r"(b[1]));
}
__device__ __forceinline__ void ldmatrix_x4(uint32_t* r, uint32_t addr) {
    asm volatile(
        "ldmatrix.sync.aligned.m8n8.x4.shared.b16 {%0,%1,%2,%3}, [%4];"
        : "=r"(r[0]), "=r"(r[1]), "=r"(r[2]), "=r"(r[3])
        : "r"(addr));
}
__device__ __forceinline__ uint32_t packh2(float lo, float hi) {
    uint32_t d;
    asm("cvt.rn.f16x2.f32 %0, %1, %2;" : "=r"(d) : "f"(hi), "f"(lo));
    return d;
}
__device__ __forceinline__ void cp16(uint32_t dst, const void* src) {
    asm volatile("cp.async.cg.shared.global [%0], [%1], 16;\n" ::"r"(dst), "l"(src));
}
#define CP_COMMIT asm volatile("cp.async.commit_group;\n")
#define CP_WAIT1 asm volatile("cp.async.wait_group 1;\n")
#define CP_WAIT0 asm volatile("cp.async.wait_group 0;\n")

// ---------------------------------------------------------------------------
// u[b,j] = sum_o h[b,o] * attn_W[o,j]   (fp32; attention path stays exact)
// ---------------------------------------------------------------------------
__global__ void __launch_bounds__(128) u_kernel(const float* __restrict__ h,
                                                const float* __restrict__ W) {
    __shared__ float hs[16][HH];
    int mb = blockIdx.x * 16;
    int j = blockIdx.y * 128 + threadIdx.x;
    for (int i = threadIdx.x; i < 16 * HH; i += 128)
        hs[i / HH][i % HH] = h[(size_t)(mb + i / HH) * HH + (i % HH)];
    __syncthreads();
    float acc[16];
#pragma unroll
    for (int m = 0; m < 16; m++) acc[m] = 0.f;
    for (int o = 0; o < HH; o++) {
        float w = W[(size_t)o * HH + j];
#pragma unroll
        for (int m = 0; m < 16; m++) acc[m] = fmaf(hs[m][o], w, acc[m]);
    }
#pragma unroll
    for (int m = 0; m < 16; m++) g_u[(size_t)(mb + m) * HH + j] = acc[m];
}

// ---------------------------------------------------------------------------
// Per-batch attention: warp-parallel scores, softmax, context.
// attn_b cancels in softmax.
// ---------------------------------------------------------------------------
__global__ void __launch_bounds__(256) attn_kernel(const float* __restrict__ enc,
                                                   const int* __restrict__ tok,
                                                   const float* __restrict__ emb,
                                                   float* __restrict__ attn_out) {
    int b = blockIdx.x;
    int t = threadIdx.x;
    int lane = t & 31, warp = t >> 5;  // 8 warps
    __shared__ float us[HH];
    __shared__ float sc[SS];
    __shared__ float wsm[SS];
    const float* encb = enc + (size_t)b * SS * HH;
    us[t] = g_u[(size_t)b * HH + t];
    us[t + 256] = g_u[(size_t)b * HH + t + 256];
    __syncthreads();

    for (int s = warp; s < SS; s += 8) {
        const float* e = encb + s * HH;
        float p = 0.f;
#pragma unroll
        for (int i = 0; i < 16; i++) p = fmaf(us[lane + i * 32], e[lane + i * 32], p);
#pragma unroll
        for (int o = 16; o > 0; o >>= 1) p += __shfl_down_sync(0xffffffffu, p, o);
        if (lane == 0) sc[s] = p;
    }
    __syncthreads();
    if (t == 0) {
        float m = -1e30f;
        for (int s = 0; s < SS; s++) m = fmaxf(m, sc[s]);
        float sum = 0.f;
        for (int s = 0; s < SS; s++) { float e = expf(sc[s] - m); wsm[s] = e; sum += e; }
        float inv = 1.f / sum;
        for (int s = 0; s < SS; s++) wsm[s] *= inv;
    }
    __syncthreads();
    if (t < SS) attn_out[(size_t)b * SS + t] = wsm[t];

    int tk = tok[b];
    const float* embrow = emb + (size_t)tk * HH;
    for (int h0 = t; h0 < HH; h0 += 256) {
        float ctx = 0.f;
#pragma unroll
        for (int s = 0; s < SS; s++) ctx = fmaf(wsm[s], encb[s * HH + h0], ctx);
        g_x[(size_t)b * 2 * HH + h0] = embrow[h0];
        g_x[(size_t)b * 2 * HH + HH + h0] = ctx;
    }
}

// ---------------------------------------------------------------------------
// Logits GEMM (fp16 mma m16n8k16): C[256,V] = A @ B^T + bias  (R13, proven)
// BM=256, BN=128, BK=32, 512 thr / 16 warps (4M x 4N), warp tile 64x32.
// A fp16 cp.async; B fp32 LDG -> packh2 -> STS fp16. B frags via ldmatrix.x4.
// ---------------------------------------------------------------------------
__global__ void __launch_bounds__(512) gemm_logits_f16(const float* __restrict__ Wf,
                                                       const float* __restrict__ bias,
                                                       float* __restrict__ C) {
    extern __shared__ char smraw[];
    uint32_t base = (uint32_t)__cvta_generic_to_shared(smraw);
    int tid = threadIdx.x;
    int lane = tid & 31, warp = tid >> 5;
    int wm = warp >> 2, wn = warp & 3;  // 4 x 4 warps
    int bn = blockIdx.x * 128;

    float acc[4][4][4];
#pragma unroll
    for (int i = 0; i < 4; i++)
#pragma unroll
        for (int j = 0; j < 4; j++)
#pragma unroll
            for (int q = 0; q < 4; q++) acc[i][j][q] = 0.f;

    int rB = tid >> 2, cB = (tid & 3) * 8;
    int gnB = bn + rB;
    const float* Bsrc = Wf + (size_t)(gnB < VV ? gnB : VV - 1) * HH + cB;
    uint32_t bSts = base + 40960u + (uint32_t)(rB * 80 + cB * 2);

    auto load_A = [&](int kt, int s) {
        int k0 = kt * 32;
#pragma unroll
        for (int it = 0; it < 2; it++) {
            int id = tid + it * 512;
            int r = id >> 2, c = id & 3;
            cp16(base + (uint32_t)(s * 20480 + r * 80 + c * 16),
                 g_hnewh + (size_t)r * HH + k0 + c * 8);
        }
        CP_COMMIT;
    };

    float4 rB0, rB1;
    auto ldg_B = [&](int kt) {
        rB0 = *(const float4*)(Bsrc + kt * 32);
        rB1 = *(const float4*)(Bsrc + kt * 32 + 4);
    };
    auto sts_B = [&](int s) {
        uint32_t h0 = packh2(rB0.x, rB0.y);
        uint32_t h1 = packh2(rB0.z, rB0.w);
        uint32_t h2 = packh2(rB1.x, rB1.y);
        uint32_t h3 = packh2(rB1.z, rB1.w);
        asm volatile("st.shared.v4.b32 [%0], {%1,%2,%3,%4};" ::"r"(bSts + (uint32_t)(s * 10240)),
                     "r"(h0), "r"(h1), "r"(h2), "r"(h3));
    };

    const int NT = HH / 32;  // 16
    load_A(0, 0);
    ldg_B(0);
    for (int kt = 0; kt < NT; kt++) {
        int s = kt & 1;
        if (kt + 1 < NT) load_A(kt + 1, s ^ 1);
        sts_B(s);
        if (kt + 1 < NT) ldg_B(kt + 1);
        if (kt + 1 < NT) { CP_WAIT1; } else { CP_WAIT0; }
        __syncthreads();
        uint32_t aBase = base + (uint32_t)(s * 20480);
        uint32_t bBase = base + (uint32_t)(40960 + s * 10240);

        uint32_t bfr[4][4];
#pragma unroll
        for (int nj = 0; nj < 4; nj++) {
            uint32_t addr = bBase +
                            (uint32_t)((wn * 32 + nj * 8 + (lane & 7)) * 80 +
                                       ((lane >> 3) << 4));
            ldmatrix_x4(bfr[nj], addr);
        }
#pragma unroll
        for (int kh = 0; kh < 2; kh++) {
            int kk = kh * 16;
            uint32_t a[4][4];
#pragma unroll
            for (int mi = 0; mi < 4; mi++) {
                int row = wm * 64 + mi * 16 + (lane & 15);
                uint32_t addr = aBase + (uint32_t)(row * 80 + (kk + ((lane >> 4) << 3)) * 2);
                ldmatrix_x4(a[mi], addr);
            }
#pragma unroll
            for (int mi = 0; mi < 4; mi++)
#pragma unroll
                for (int nj = 0; nj < 4; nj++)
                    mma_sync_f16(acc[mi][nj], a[mi], &bfr[nj][kh * 2]);
        }
        __syncthreads();
    }

    // Bias add
#pragma unroll
    for (int nj = 0; nj < 4; nj++) {
        int col = bn + wn * 32 + nj * 8 + (lane & 3) * 2;
        float bv0 = (col < VV) ? bias[col] : 0.f;
        float bv1 = (col + 1 < VV) ? bias[col + 1] : 0.f;
#pragma unroll
        for (int mi = 0; mi < 4; mi++) {
            acc[mi][nj][0] += bv0;
            acc[mi][nj][1] += bv1;
            acc[mi][nj][2] += bv0;
            acc[mi][nj][3] += bv1;
        }
    }

    // Epilogue: smem stage halves, stride-32 coalesced stores + lse partials
    float* smC = (float*)smraw;  // [128][132]
#pragma unroll 1
    for (int half = 0; half < 2; half++) {
        __syncthreads();
        if ((wm >> 1) == half) {
            int rbase = (wm & 1) * 64;
#pragma unroll
            for (int mi = 0; mi < 4; mi++) {
                int rowl = rbase + mi * 16 + (lane >> 2);
#pragma unroll
                for (int nj = 0; nj < 4; nj++) {
                    int coll = wn * 32 + nj * 8 + (lane & 3) * 2;
                    *(float2*)(smC + rowl * 132 + coll) =
                        make_float2(acc[mi][nj][0], acc[mi][nj][1]);
                    *(float2*)(smC + (rowl + 8) * 132 + coll) =
                        make_float2(acc[mi][nj][2], acc[mi][nj][3]);
                }
            }
        }
        __syncthreads();
#pragma unroll 1
        for (int rr = 0; rr < 8; rr++) {
            int rowl = warp * 8 + rr;
            int grow = half * 128 + rowl;
            float vals[4];
            float m = -1e30f;
#pragma unroll
            for (int e = 0; e < 4; e++) {
                int col = lane + e * 32;
                vals[e] = smC[rowl * 132 + col];
                if (bn + col < VV) m = fmaxf(m, vals[e]);
            }
            float s = 0.f;
#pragma unroll
            for (int e = 0; e < 4; e++)
                if (bn + lane + e * 32 < VV) s += __expf(vals[e] - m);
#pragma unroll
            for (int o = 16; o > 0; o >>= 1) {
                float om = __shfl_down_sync(0xffffffffu, m, o);
                float os = __shfl_down_sync(0xffffffffu, s, o);
                float nm = fmaxf(m, om);
                s = s * __expf(m - nm) + os * __expf(om - nm);
                m = nm;
            }
            if (lane == 0) {
                g_pm[(size_t)grow * NBX + blockIdx.x] = m;
                g_ps[(size_t)grow * NBX + blockIdx.x] = s;
            }
#pragma unroll
            for (int e = 0; e < 4; e++) {
                int col = bn + lane + e * 32;
                if (col < VV) C[(size_t)grow * VV + col] = vals[e];
            }
        }
    }
}

// ---------------------------------------------------------------------------
// Merge per-block lse partials -> g_lse[b]
// ---------------------------------------------------------------------------
__global__ void __launch_bounds__(128) reduce_lse() {
    int b = blockIdx.x, t = threadIdx.x;
    int lane = t & 31, warp = t >> 5;
    __shared__ float sm_m[4], sm_s[4];
    float m = -1e30f, s = 0.f;
    for (int i = t; i < NBX; i += 128) {
        float pm = g_pm[(size_t)b * NBX + i];
        float ps = g_ps[(size_t)b * NBX + i];
        float nm = fmaxf(m, pm);
        s = s * __expf(m - nm) + ps * __expf(pm - nm);
        m = nm;
    }
#pragma unroll
    for (int o = 16; o > 0; o >>= 1) {
        float om = __shfl_down_sync(0xffffffffu, m, o);
        float os = __shfl_down_sync(0xffffffffu, s, o);
        float nm = fmaxf(m, om);
        s = s * __expf(m - nm) + os * __expf(om - nm);
        m = nm;
    }
    if (lane == 0) { sm_m[warp] = m; sm_s[warp] = s; }
    __syncthreads();
    if (t == 0) {
        float M = sm_m[0], S = sm_s[0];
#pragma unroll
        for (int w = 1; w < 4; w++) {
            float nm = fmaxf(M, sm_m[w]);
            S = S * __expf(M - nm) + sm_s[w] * __expf(sm_m[w] - nm);
            M = nm;
        }
        g_lse[b] = M + logf(S);
    }
}

// log_probs = logits - lse[b]; 8 strided elems/thread (fewer blocks)
__global__ void __launch_bounds__(256) sub_kernel(float* __restrict__ lg) {
    int b = blockIdx.y;
    int c0 = blockIdx.x * 2048 + threadIdx.x;
    float lse = g_lse[b];
    float* row = lg + (size_t)b * VV;
#pragma unroll
    for (int e = 0; e < 8; e++) {
        int c = c0 + e * 256;
        if (c < VV) row[c] -= lse;
    }
}

// ---------------------------------------------------------------------------
// GRU gate GEMMs (fp16 m16n8k16), split by source via blockIdx.z:
//   z=0: g_gi = x @ W_ih^T + b_ih  (K=1024)
//   z=1: g_gh = h @ W_hh^T + b_hh  (K=512)
// BM=64 BN=64 BK=32, 128 thr, 4 warps (2M x 2N), warp tile 32x32.
// Both operands: fp32 LDG -> packh2 -> STS fp16 (same mantissa as tf32).
// smem: A stage s at s*5120 (64 rows x 80B); B at 10240 + s*5120. 20480 B.
// ---------------------------------------------------------------------------
__global__ void __launch_bounds__(128) gemm_gru(const float* __restrict__ Xp,
                                                const float* __restrict__ Hp,
                                                const float* __restrict__ Wih,
                                                const float* __restrict__ Whh,
                                                const float* __restrict__ bih,
                                                const float* __restrict__ bhh) {
    __shared__ __align__(16) char sm[20480];
    uint32_t base = (uint32_t)__cvta_generic_to_shared(sm);
    int tid = threadIdx.x, lane = tid & 31, warp = tid >> 5;
    int wm = warp >> 1, wn = warp & 1;
    int bm = blockIdx.x * 64, bn = blockIdx.y * 64;
    int which = blockIdx.z;

    const float* Ap = which ? Hp : Xp;
    const float* Bp = which ? Whh : Wih;
    const float* bias = which ? bhh : bih;
    float* outp = which ? g_gh : g_gi;
    const int K = which ? HH : 2 * HH;
    const int NT = K / 32;

    float acc[2][4][4];
#pragma unroll
    for (int i = 0; i < 2; i++)
#pragma unroll
        for (int j = 0; j < 4; j++)
#pragma unroll
            for (int q = 0; q < 4; q++) acc[i][j][q] = 0.f;

    // per-thread staging slice: row = tid>>1 (0..63), half = tid&1 -> 16 floats
    int rS = tid >> 1, hS = tid & 1;
    const float* Asrc = Ap + (size_t)(bm + rS) * K + hS * 16;
    const float* Bsrc = Bp + (size_t)(bn + rS) * K + hS * 16;
    uint32_t aSts = base + (uint32_t)(rS * 80 + hS * 32);
    uint32_t bSts = base + 10240u + (uint32_t)(rS * 80 + hS * 32);

    float4 rA[4], rBv[4];
    auto ldg_AB = [&](int kt) {
        int k0 = kt * 32;
#pragma unroll
        for (int e = 0; e < 4; e++) rA[e] = *(const float4*)(Asrc + k0 + e * 4);
#pragma unroll
        for (int e = 0; e < 4; e++) rBv[e] = *(const float4*)(Bsrc + k0 + e * 4);
    };
    auto sts_AB = [&](int s) {
        uint32_t off = (uint32_t)(s * 5120);
        uint32_t a0 = packh2(rA[0].x, rA[0].y), a1 = packh2(rA[0].z, rA[0].w);
        uint32_t a2 = packh2(rA[1].x, rA[1].y), a3 = packh2(rA[1].z, rA[1].w);
        asm volatile("st.shared.v4.b32 [%0], {%1,%2,%3,%4};" ::"r"(aSts + off),
                     "r"(a0), "r"(a1), "r"(a2), "r"(a3));
        a0 = packh2(rA[2].x, rA[2].y); a1 = packh2(rA[2].z, rA[2].w);
        a2 = packh2(rA[3].x, rA[3].y); a3 = packh2(rA[3].z, rA[3].w);
        asm volatile("st.shared.v4.b32 [%0], {%1,%2,%3,%4};" ::"r"(aSts + off + 16),
                     "r"(a0), "r"(a1), "r"(a2), "r"(a3));
        uint32_t b0 = packh2(rBv[0].x, rBv[0].y), b1 = packh2(rBv[0].z, rBv[0].w);
        uint32_t b2 = packh2(rBv[1].x, rBv[1].y), b3 = packh2(rBv[1].z, rBv[1].w);
        asm volatile("st.shared.v4.b32 [%0], {%1,%2,%3,%4};" ::"r"(bSts + off),
                     "r"(b0), "r"(b1), "r"(b2), "r"(b3));
        b0 = packh2(rBv[2].x, rBv[2].y); b1 = packh2(rBv[2].z, rBv[2].w);
        b2 = packh2(rBv[3].x, rBv[3].y); b3 = packh2(rBv[3].z, rBv[3].w);
        asm volatile("st.shared.v4.b32 [%0], {%1,%2,%3,%4};" ::"r"(bSts + off + 16),
                     "r"(b0), "r"(b1), "r"(b2), "r"(b3));
    };

    ldg_AB(0);
    for (int kt = 0; kt < NT; kt++) {
        int s = kt & 1;
        sts_AB(s);
        if (kt + 1 < NT) ldg_AB(kt + 1);
        __syncthreads();
        uint32_t aBase = base + (uint32_t)(s * 5120);
        uint32_t bBase = base + 10240u + (uint32_t)(s * 5120);

        // B fragments: one ldmatrix.x4 per nj covers both kk halves
        uint32_t bfr[4][4];
#pragma unroll
        for (int nj = 0; nj < 4; nj++) {
            uint32_t addr = bBase +
                            (uint32_t)((wn * 32 + nj * 8 + (lane & 7)) * 80 +
                                       ((lane >> 3) << 4));
            ldmatrix_x4(bfr[nj], addr);
        }
#pragma unroll
        for (int kh = 0; kh < 2; kh++) {
            int kk = kh * 16;
            uint32_t a[2][4];
#pragma unroll
            for (int mi = 0; mi < 2; mi++) {
                int row = wm * 32 + mi * 16 + (lane & 15);
                uint32_t addr = aBase + (uint32_t)(row * 80 + (kk + ((lane >> 4) << 3)) * 2);
                ldmatrix_x4(a[mi], addr);
            }
#pragma unroll
            for (int mi = 0; mi < 2; mi++)
#pragma unroll
                for (int nj = 0; nj < 4; nj++)
                    mma_sync_f16(acc[mi][nj], a[mi], &bfr[nj][kh * 2]);
        }
        __syncthreads();
    }

    const int N = 3 * HH;
    int gr = lane >> 2, tg = lane & 3;
#pragma unroll
    for (int i = 0; i < 2; i++) {
#pragma unroll
        for (int j = 0; j < 4; j++) {
            int row = bm + wm * 32 + i * 16 + gr;
            int col = bn + wn * 32 + j * 8 + tg * 2;
#pragma unroll
            for (int q = 0; q < 2; q++) {
                int cc = col + q;
                float bv = bias[cc];
                outp[(size_t)row * N + cc] = acc[i][j][q] + bv;
                outp[(size_t)(row + 8) * N + cc] = acc[i][j][q + 2] + bv;
            }
        }
    }
}

// ---------------------------------------------------------------------------
// GRU gates: writes fp32 h_new (output) and fp16 copy (GEMM operand)
// ---------------------------------------------------------------------------
__global__ void __launch_bounds__(256) gate_kernel(const float* __restrict__ hprev,
                                                   float* __restrict__ out_h) {
    int idx = blockIdx.x * 256 + threadIdx.x;
    int b = idx >> 9, j = idx & 511;
    size_t gi0 = (size_t)b * 3 * HH + j;
    float i_r = g_gi[gi0], i_z = g_gi[gi0 + HH], i_n = g_gi[gi0 + 2 * HH];
    float h_r = g_gh[gi0], h_z = g_gh[gi0 + HH], h_n = g_gh[gi0 + 2 * HH];
    float r = 1.f / (1.f + expf(-(i_r + h_r)));
    float z = 1.f / (1.f + expf(-(i_z + h_z)));
    float n = tanhf(i_n + r * h_n);
    float h = hprev[idx];
    float hn = (1.f - z) * n + z * h;
    g_hnewh[idx] = __float2half_rn(hn);
    out_h[idx] = hn;
}

// ---------------------------------------------------------------------------
extern "C" void kernel_launch(void* const* d_in, const int* in_sizes, int n_in,
                              void* d_out, int out_size) {
    (void)in_sizes; (void)n_in; (void)out_size;
    const int*   tok    = (const int*)d_in[0];
    const float* hidden = (const float*)d_in[1];
    const float* enc    = (const float*)d_in[2];
    const float* emb    = (const float*)d_in[3];
    const float* attnW  = (const float*)d_in[4];
    // d_in[5] = attn_b: unused (cancels in softmax)
    const float* W_ih   = (const float*)d_in[6];
    const float* W_hh   = (const float*)d_in[7];
    const float* b_ih   = (const float*)d_in[8];
    const float* b_hh   = (const float*)d_in[9];
    const float* out_W  = (const float*)d_in[10];
    const float* out_b  = (const float*)d_in[11];

    float* out        = (float*)d_out;
    float* out_logits = out;
    float* out_h      = out + (size_t)BB * VV;
    float* out_attn   = out_h + (size_t)BB * HH;

    float* p_x;
    cudaGetSymbolAddress((void**)&p_x, g_x);

    cudaFuncSetAttribute(gemm_logits_f16, cudaFuncAttributeMaxDynamicSharedMemorySize,
                         67584);

    // 1) u = h @ attn_W (fp32)
    u_kernel<<<dim3(16, 4), 128>>>(hidden, attnW);
    // 2) softmax attention -> attn_weights + x (warp-parallel scores)
    attn_kernel<<<BB, 256>>>(enc, tok, emb, out_attn);
    // 3) GRU gate GEMMs (fp16 mma, STS-time convert), K-split by z
    gemm_gru<<<dim3(4, 24, 2), 128>>>(p_x, hidden, W_ih, W_hh, b_ih, b_hh);
    // 4) gates -> h_new (fp32 out + fp16 operand)
    gate_kernel<<<(BB * HH) / 256, 256>>>(hidden, out_h);
    // 5) logits: fp16 mma (BM=256), B frags via ldmatrix, fused lse partials
    gemm_logits_f16<<<NBX, 512, 67584>>>(out_W, out_b, out_logits);
    // 6) finish log_softmax
    reduce_lse<<<BB, 128>>>();
    sub_kernel<<<dim3((VV + 2047) / 2048, BB), 256>>>(out_logits);
}

// round 16
// speedup vs baseline: 1.0442x; 1.0442x over previous
#include <cuda_runtime.h>
#include <cuda_fp16.h>
#include <math.h>
#include <stdint.h>

#define BB 256
#define SS 15
#define HH 512
#define VV 50257
#define NBX 393  // (VV + 127) / 128

// Scratch (device globals: no allocation allowed)
__device__ float g_u[BB * HH];
__device__ float g_x[BB * 2 * HH];
__device__ __align__(128) float g_gi[BB * 3 * HH];
__device__ __align__(128) float g_gh[BB * 3 * HH];
__device__ __align__(128) __half g_hnewh[BB * HH];
__device__ float g_pm[BB * NBX];
__device__ float g_ps[BB * NBX];
__device__ float g_lse[BB];

// ---------------------------------------------------------------------------
// helpers
// ---------------------------------------------------------------------------
__device__ __forceinline__ float to_tf32(float x) {
    float y;
    asm("cvt.rna.tf32.f32 %0, %1;" : "=f"(y) : "f"(x));
    return y;
}
__device__ __forceinline__ uint32_t ldtf(const float* p) {
    return __float_as_uint(to_tf32(*p));
}
__device__ __forceinline__ void mma_sync_tf32(float* d, const uint32_t* a, const uint32_t* b) {
    asm volatile(
        "mma.sync.aligned.m16n8k8.row.col.f32.tf32.tf32.f32 "
        "{%0,%1,%2,%3},{%4,%5,%6,%7},{%8,%9},{%0,%1,%2,%3};\n"
        : "+f"(d[0]), "+f"(d[1]), "+f"(d[2]), "+f"(d[3])
        : "r"(a[0]), "r"(a[1]), "r"(a[2]), "r"(a[3]), "r"(b[0]), "r"(b[1]));
}
__device__ __forceinline__ void mma_sync_f16(float* d, const uint32_t* a, const uint32_t* b) {
    asm volatile(
        "mma.sync.aligned.m16n8k16.row.col.f32.f16.f16.f32 "
        "{%0,%1,%2,%3},{%4,%5,%6,%7},{%8,%9},{%0,%1,%2,%3};\n"
        : "+f"(d[0]), "+f"(d[1]), "+f"(d[2]), "+f"(d[3])
        : "r"(a[0]), "r"(a[1]), "r"(a[2]), "r"(a[3]), "r"(b[0]), "r"(b[1]));
}
__device__ __forceinline__ void ldmatrix_x4(uint32_t* r, uint32_t addr) {
    asm volatile(
        "ldmatrix.sync.aligned.m8n8.x4.shared.b16 {%0,%1,%2,%3}, [%4];"
        : "=r"(r[0]), "=r"(r[1]), "=r"(r[2]), "=r"(r[3])
        : "r"(addr));
}
__device__ __forceinline__ uint32_t packh2(float lo, float hi) {
    uint32_t d;
    asm("cvt.rn.f16x2.f32 %0, %1, %2;" : "=r"(d) : "f"(hi), "f"(lo));
    return d;
}
__device__ __forceinline__ void cp16(uint32_t dst, const void* src) {
    asm volatile("cp.async.cg.shared.global [%0], [%1], 16;\n" ::"r"(dst), "l"(src));
}
#define CP_COMMIT asm volatile("cp.async.commit_group;\n")
#define CP_WAIT1 asm volatile("cp.async.wait_group 1;\n")
#define CP_WAIT0 asm volatile("cp.async.wait_group 0;\n")

// ---------------------------------------------------------------------------
// u[b,j] = sum_o h[b,o] * attn_W[o,j]   (fp32; attention path stays exact)
// ---------------------------------------------------------------------------
__global__ void __launch_bounds__(128) u_kernel(const float* __restrict__ h,
                                                const float* __restrict__ W) {
    __shared__ float hs[16][HH];
    int mb = blockIdx.x * 16;
    int j = blockIdx.y * 128 + threadIdx.x;
    for (int i = threadIdx.x; i < 16 * HH; i += 128)
        hs[i / HH][i % HH] = h[(size_t)(mb + i / HH) * HH + (i % HH)];
    __syncthreads();
    float acc[16];
#pragma unroll
    for (int m = 0; m < 16; m++) acc[m] = 0.f;
    for (int o = 0; o < HH; o++) {
        float w = W[(size_t)o * HH + j];
#pragma unroll
        for (int m = 0; m < 16; m++) acc[m] = fmaf(hs[m][o], w, acc[m]);
    }
#pragma unroll
    for (int m = 0; m < 16; m++) g_u[(size_t)(mb + m) * HH + j] = acc[m];
}

// ---------------------------------------------------------------------------
// Per-batch attention: warp-parallel scores, softmax, context.
// attn_b cancels in softmax.
// ---------------------------------------------------------------------------
__global__ void __launch_bounds__(256) attn_kernel(const float* __restrict__ enc,
                                                   const int* __restrict__ tok,
                                                   const float* __restrict__ emb,
                                                   float* __restrict__ attn_out) {
    int b = blockIdx.x;
    int t = threadIdx.x;
    int lane = t & 31, warp = t >> 5;  // 8 warps
    __shared__ float us[HH];
    __shared__ float sc[SS];
    __shared__ float wsm[SS];
    const float* encb = enc + (size_t)b * SS * HH;
    us[t] = g_u[(size_t)b * HH + t];
    us[t + 256] = g_u[(size_t)b * HH + t + 256];
    __syncthreads();

    for (int s = warp; s < SS; s += 8) {
        const float* e = encb + s * HH;
        float p = 0.f;
#pragma unroll
        for (int i = 0; i < 16; i++) p = fmaf(us[lane + i * 32], e[lane + i * 32], p);
#pragma unroll
        for (int o = 16; o > 0; o >>= 1) p += __shfl_down_sync(0xffffffffu, p, o);
        if (lane == 0) sc[s] = p;
    }
    __syncthreads();
    if (t == 0) {
        float m = -1e30f;
        for (int s = 0; s < SS; s++) m = fmaxf(m, sc[s]);
        float sum = 0.f;
        for (int s = 0; s < SS; s++) { float e = expf(sc[s] - m); wsm[s] = e; sum += e; }
        float inv = 1.f / sum;
        for (int s = 0; s < SS; s++) wsm[s] *= inv;
    }
    __syncthreads();
    if (t < SS) attn_out[(size_t)b * SS + t] = wsm[t];

    int tk = tok[b];
    const float* embrow = emb + (size_t)tk * HH;
    for (int h0 = t; h0 < HH; h0 += 256) {
        float ctx = 0.f;
#pragma unroll
        for (int s = 0; s < SS; s++) ctx = fmaf(wsm[s], encb[s * HH + h0], ctx);
        g_x[(size_t)b * 2 * HH + h0] = embrow[h0];
        g_x[(size_t)b * 2 * HH + HH + h0] = ctx;
    }
}

// ---------------------------------------------------------------------------
// Logits GEMM (fp16 mma m16n8k16): C[256,V] = A @ B^T + bias  (R13, proven)
// BM=256, BN=128, BK=32, 512 thr / 16 warps (4M x 4N), warp tile 64x32.
// A fp16 cp.async; B fp32 LDG -> packh2 -> STS fp16. B frags via ldmatrix.x4.
// ---------------------------------------------------------------------------
__global__ void __launch_bounds__(512) gemm_logits_f16(const float* __restrict__ Wf,
                                                       const float* __restrict__ bias,
                                                       float* __restrict__ C) {
    extern __shared__ char smraw[];
    uint32_t base = (uint32_t)__cvta_generic_to_shared(smraw);
    int tid = threadIdx.x;
    int lane = tid & 31, warp = tid >> 5;
    int wm = warp >> 2, wn = warp & 3;  // 4 x 4 warps
    int bn = blockIdx.x * 128;

    float acc[4][4][4];
#pragma unroll
    for (int i = 0; i < 4; i++)
#pragma unroll
        for (int j = 0; j < 4; j++)
#pragma unroll
            for (int q = 0; q < 4; q++) acc[i][j][q] = 0.f;

    int rB = tid >> 2, cB = (tid & 3) * 8;
    int gnB = bn + rB;
    const float* Bsrc = Wf + (size_t)(gnB < VV ? gnB : VV - 1) * HH + cB;
    uint32_t bSts = base + 40960u + (uint32_t)(rB * 80 + cB * 2);

    auto load_A = [&](int kt, int s) {
        int k0 = kt * 32;
#pragma unroll
        for (int it = 0; it < 2; it++) {
            int id = tid + it * 512;
            int r = id >> 2, c = id & 3;
            cp16(base + (uint32_t)(s * 20480 + r * 80 + c * 16),
                 g_hnewh + (size_t)r * HH + k0 + c * 8);
        }
        CP_COMMIT;
    };

    float4 rB0, rB1;
    auto ldg_B = [&](int kt) {
        rB0 = *(const float4*)(Bsrc + kt * 32);
        rB1 = *(const float4*)(Bsrc + kt * 32 + 4);
    };
    auto sts_B = [&](int s) {
        uint32_t h0 = packh2(rB0.x, rB0.y);
        uint32_t h1 = packh2(rB0.z, rB0.w);
        uint32_t h2 = packh2(rB1.x, rB1.y);
        uint32_t h3 = packh2(rB1.z, rB1.w);
        asm volatile("st.shared.v4.b32 [%0], {%1,%2,%3,%4};" ::"r"(bSts + (uint32_t)(s * 10240)),
                     "r"(h0), "r"(h1), "r"(h2), "r"(h3));
    };

    const int NT = HH / 32;  // 16
    load_A(0, 0);
    ldg_B(0);
    for (int kt = 0; kt < NT; kt++) {
        int s = kt & 1;
        if (kt + 1 < NT) load_A(kt + 1, s ^ 1);
        sts_B(s);
        if (kt + 1 < NT) ldg_B(kt + 1);
        if (kt + 1 < NT) { CP_WAIT1; } else { CP_WAIT0; }
        __syncthreads();
        uint32_t aBase = base + (uint32_t)(s * 20480);
        uint32_t bBase = base + (uint32_t)(40960 + s * 10240);

        uint32_t bfr[4][4];
#pragma unroll
        for (int nj = 0; nj < 4; nj++) {
            uint32_t addr = bBase +
                            (uint32_t)((wn * 32 + nj * 8 + (lane & 7)) * 80 +
                                       ((lane >> 3) << 4));
            ldmatrix_x4(bfr[nj], addr);
        }
#pragma unroll
        for (int kh = 0; kh < 2; kh++) {
            int kk = kh * 16;
            uint32_t a[4][4];
#pragma unroll
            for (int mi = 0; mi < 4; mi++) {
                int row = wm * 64 + mi * 16 + (lane & 15);
                uint32_t addr = aBase + (uint32_t)(row * 80 + (kk + ((lane >> 4) << 3)) * 2);
                ldmatrix_x4(a[mi], addr);
            }
#pragma unroll
            for (int mi = 0; mi < 4; mi++)
#pragma unroll
                for (int nj = 0; nj < 4; nj++)
                    mma_sync_f16(acc[mi][nj], a[mi], &bfr[nj][kh * 2]);
        }
        __syncthreads();
    }

    // Bias add
#pragma unroll
    for (int nj = 0; nj < 4; nj++) {
        int col = bn + wn * 32 + nj * 8 + (lane & 3) * 2;
        float bv0 = (col < VV) ? bias[col] : 0.f;
        float bv1 = (col + 1 < VV) ? bias[col + 1] : 0.f;
#pragma unroll
        for (int mi = 0; mi < 4; mi++) {
            acc[mi][nj][0] += bv0;
            acc[mi][nj][1] += bv1;
            acc[mi][nj][2] += bv0;
            acc[mi][nj][3] += bv1;
        }
    }

    // Epilogue: smem stage halves, stride-32 coalesced stores + lse partials
    float* smC = (float*)smraw;  // [128][132]
#pragma unroll 1
    for (int half = 0; half < 2; half++) {
        __syncthreads();
        if ((wm >> 1) == half) {
            int rbase = (wm & 1) * 64;
#pragma unroll
            for (int mi = 0; mi < 4; mi++) {
                int rowl = rbase + mi * 16 + (lane >> 2);
#pragma unroll
                for (int nj = 0; nj < 4; nj++) {
                    int coll = wn * 32 + nj * 8 + (lane & 3) * 2;
                    *(float2*)(smC + rowl * 132 + coll) =
                        make_float2(acc[mi][nj][0], acc[mi][nj][1]);
                    *(float2*)(smC + (rowl + 8) * 132 + coll) =
                        make_float2(acc[mi][nj][2], acc[mi][nj][3]);
                }
            }
        }
        __syncthreads();
#pragma unroll 1
        for (int rr = 0; rr < 8; rr++) {
            int rowl = warp * 8 + rr;
            int grow = half * 128 + rowl;
            float vals[4];
            float m = -1e30f;
#pragma unroll
            for (int e = 0; e < 4; e++) {
                int col = lane + e * 32;
                vals[e] = smC[rowl * 132 + col];
                if (bn + col < VV) m = fmaxf(m, vals[e]);
            }
            float s = 0.f;
#pragma unroll
            for (int e = 0; e < 4; e++)
                if (bn + lane + e * 32 < VV) s += __expf(vals[e] - m);
#pragma unroll
            for (int o = 16; o > 0; o >>= 1) {
                float om = __shfl_down_sync(0xffffffffu, m, o);
                float os = __shfl_down_sync(0xffffffffu, s, o);
                float nm = fmaxf(m, om);
                s = s * __expf(m - nm) + os * __expf(om - nm);
                m = nm;
            }
            if (lane == 0) {
                g_pm[(size_t)grow * NBX + blockIdx.x] = m;
                g_ps[(size_t)grow * NBX + blockIdx.x] = s;
            }
#pragma unroll
            for (int e = 0; e < 4; e++) {
                int col = bn + lane + e * 32;
                if (col < VV) C[(size_t)grow * VV + col] = vals[e];
            }
        }
    }
}

// ---------------------------------------------------------------------------
// Merge per-block lse partials -> g_lse[b]
// ---------------------------------------------------------------------------
__global__ void __launch_bounds__(128) reduce_lse() {
    int b = blockIdx.x, t = threadIdx.x;
    int lane = t & 31, warp = t >> 5;
    __shared__ float sm_m[4], sm_s[4];
    float m = -1e30f, s = 0.f;
    for (int i = t; i < NBX; i += 128) {
        float pm = g_pm[(size_t)b * NBX + i];
        float ps = g_ps[(size_t)b * NBX + i];
        float nm = fmaxf(m, pm);
        s = s * __expf(m - nm) + ps * __expf(pm - nm);
        m = nm;
    }
#pragma unroll
    for (int o = 16; o > 0; o >>= 1) {
        float om = __shfl_down_sync(0xffffffffu, m, o);
        float os = __shfl_down_sync(0xffffffffu, s, o);
        float nm = fmaxf(m, om);
        s = s * __expf(m - nm) + os * __expf(om - nm);
        m = nm;
    }
    if (lane == 0) { sm_m[warp] = m; sm_s[warp] = s; }
    __syncthreads();
    if (t == 0) {
        float M = sm_m[0], S = sm_s[0];
#pragma unroll
        for (int w = 1; w < 4; w++) {
            float nm = fmaxf(M, sm_m[w]);
            S = S * __expf(M - nm) + sm_s[w] * __expf(sm_m[w] - nm);
            M = nm;
        }
        g_lse[b] = M + logf(S);
    }
}

// log_probs = logits - lse[b]; scalar, coalesced, alignment-free (R13)
__global__ void __launch_bounds__(256) sub_kernel(float* __restrict__ lg) {
    int b = blockIdx.y;
    int c = blockIdx.x * 256 + threadIdx.x;
    if (c < VV) lg[(size_t)b * VV + c] -= g_lse[b];
}

// ---------------------------------------------------------------------------
// GRU gate GEMMs, tf32 + cp.async double-buffer, split by blockIdx.z (R13)
// ---------------------------------------------------------------------------
#define LST 36

__global__ void __launch_bounds__(128) gemm_gru(const float* __restrict__ Xp,
                                                const float* __restrict__ Hp,
                                                const float* __restrict__ Wih,
                                                const float* __restrict__ Whh,
                                                const float* __restrict__ bih,
                                                const float* __restrict__ bhh) {
    __shared__ float As[2][64][LST];
    __shared__ float Bs[2][64][LST];
    int tid = threadIdx.x, lane = tid & 31, warp = tid >> 5;
    int wm = warp >> 1, wn = warp & 1;
    int gr = lane >> 2, tg = lane & 3;
    int bm = blockIdx.x * 64, bn = blockIdx.y * 64;
    int which = blockIdx.z;

    const float* Ap = which ? Hp : Xp;
    const float* Bp = which ? Whh : Wih;
    const float* bias = which ? bhh : bih;
    float* outp = which ? g_gh : g_gi;
    const int K = which ? HH : 2 * HH;
    const int NT = K / 32;

    uint32_t asB = (uint32_t)__cvta_generic_to_shared(&As[0][0][0]);
    uint32_t bsB = (uint32_t)__cvta_generic_to_shared(&Bs[0][0][0]);

    float acc[2][4][4];
#pragma unroll
    for (int i = 0; i < 2; i++)
#pragma unroll
        for (int j = 0; j < 4; j++)
#pragma unroll
            for (int q = 0; q < 4; q++) acc[i][j][q] = 0.f;

    auto load_tile = [&](int kt, int s) {
        int k0 = kt * 32;
#pragma unroll
        for (int it = 0; it < 4; it++) {
            int id = tid + it * 128;
            int r = id >> 3, c = id & 7;
            cp16(asB + (((s * 64 + r) * LST) + c * 4) * 4,
                 Ap + (size_t)(bm + r) * K + k0 + c * 4);
        }
#pragma unroll
        for (int it = 0; it < 4; it++) {
            int id = tid + it * 128;
            int r = id >> 3, c = id & 7;
            cp16(bsB + (((s * 64 + r) * LST) + c * 4) * 4,
                 Bp + (size_t)(bn + r) * K + k0 + c * 4);
        }
        CP_COMMIT;
    };

    load_tile(0, 0);
    for (int kt = 0; kt < NT; kt++) {
        if (kt + 1 < NT) { load_tile(kt + 1, (kt + 1) & 1); CP_WAIT1; }
        else { CP_WAIT0; }
        __syncthreads();
        int s = kt & 1;
#pragma unroll
        for (int kk = 0; kk < 32; kk += 8) {
            uint32_t a[2][4], b[4][2];
#pragma unroll
            for (int i = 0; i < 2; i++) {
                const float* r0 = &As[s][wm * 32 + i * 16 + gr][kk];
                a[i][0] = ldtf(r0 + tg);
                a[i][1] = ldtf(r0 + 8 * LST + tg);
                a[i][2] = ldtf(r0 + tg + 4);
                a[i][3] = ldtf(r0 + 8 * LST + tg + 4);
            }
#pragma unroll
            for (int j = 0; j < 4; j++) {
                const float* c0 = &Bs[s][wn * 32 + j * 8 + gr][kk];
                b[j][0] = ldtf(c0 + tg);
                b[j][1] = ldtf(c0 + tg + 4);
            }
#pragma unroll
            for (int i = 0; i < 2; i++)
#pragma unroll
                for (int j = 0; j < 4; j++) mma_sync_tf32(acc[i][j], a[i], b[j]);
        }
        __syncthreads();
    }

    const int N = 3 * HH;
#pragma unroll
    for (int i = 0; i < 2; i++) {
#pragma unroll
        for (int j = 0; j < 4; j++) {
            int row = bm + wm * 32 + i * 16 + gr;
            int col = bn + wn * 32 + j * 8 + tg * 2;
#pragma unroll
            for (int q = 0; q < 2; q++) {
                int cc = col + q;
                float bv = bias[cc];
                outp[(size_t)row * N + cc] = acc[i][j][q] + bv;
                outp[(size_t)(row + 8) * N + cc] = acc[i][j][q + 2] + bv;
            }
        }
    }
}

// ---------------------------------------------------------------------------
// GRU gates, vectorized 4 elems/thread (float4; all offsets 16B-aligned).
// Writes fp32 h_new (output) and fp16 copy (GEMM operand).
// ---------------------------------------------------------------------------
__global__ void __launch_bounds__(256) gate_kernel(const float* __restrict__ hprev,
                                                   float* __restrict__ out_h) {
    int idx = (blockIdx.x * 256 + threadIdx.x) * 4;  // 0 .. B*H-1, step 4
    int b = idx >> 9, j = idx & 511;
    size_t gi0 = (size_t)b * 3 * HH + j;
    float4 i_r = *(const float4*)(g_gi + gi0);
    float4 i_z = *(const float4*)(g_gi + gi0 + HH);
    float4 i_n = *(const float4*)(g_gi + gi0 + 2 * HH);
    float4 h_r = *(const float4*)(g_gh + gi0);
    float4 h_z = *(const float4*)(g_gh + gi0 + HH);
    float4 h_n = *(const float4*)(g_gh + gi0 + 2 * HH);
    float4 hp = *(const float4*)(hprev + idx);

    float hn[4];
    {
        const float ir[4] = {i_r.x, i_r.y, i_r.z, i_r.w};
        const float iz[4] = {i_z.x, i_z.y, i_z.z, i_z.w};
        const float in_[4] = {i_n.x, i_n.y, i_n.z, i_n.w};
        const float hr[4] = {h_r.x, h_r.y, h_r.z, h_r.w};
        const float hz[4] = {h_z.x, h_z.y, h_z.z, h_z.w};
        const float hnn[4] = {h_n.x, h_n.y, h_n.z, h_n.w};
        const float hh[4] = {hp.x, hp.y, hp.z, hp.w};
#pragma unroll
        for (int e = 0; e < 4; e++) {
            float r = 1.f / (1.f + expf(-(ir[e] + hr[e])));
            float z = 1.f / (1.f + expf(-(iz[e] + hz[e])));
            float n = tanhf(in_[e] + r * hnn[e]);
            hn[e] = (1.f - z) * n + z * hh[e];
        }
    }
    *(float4*)(out_h + idx) = make_float4(hn[0], hn[1], hn[2], hn[3]);
    uint32_t p0 = packh2(hn[0], hn[1]);
    uint32_t p1 = packh2(hn[2], hn[3]);
    *(uint2*)(g_hnewh + idx) = make_uint2(p0, p1);
}

// ---------------------------------------------------------------------------
extern "C" void kernel_launch(void* const* d_in, const int* in_sizes, int n_in,
                              void* d_out, int out_size) {
    (void)in_sizes; (void)n_in; (void)out_size;
    const int*   tok    = (const int*)d_in[0];
    const float* hidden = (const float*)d_in[1];
    const float* enc    = (const float*)d_in[2];
    const float* emb    = (const float*)d_in[3];
    const float* attnW  = (const float*)d_in[4];
    // d_in[5] = attn_b: unused (cancels in softmax)
    const float* W_ih   = (const float*)d_in[6];
    const float* W_hh   = (const float*)d_in[7];
    const float* b_ih   = (const float*)d_in[8];
    const float* b_hh   = (const float*)d_in[9];
    const float* out_W  = (const float*)d_in[10];
    const float* out_b  = (const float*)d_in[11];

    float* out        = (float*)d_out;
    float* out_logits = out;
    float* out_h      = out + (size_t)BB * VV;
    float* out_attn   = out_h + (size_t)BB * HH;

    float* p_x;
    cudaGetSymbolAddress((void**)&p_x, g_x);

    cudaFuncSetAttribute(gemm_logits_f16, cudaFuncAttributeMaxDynamicSharedMemorySize,
                         67584);

    // 1) u = h @ attn_W (fp32)
    u_kernel<<<dim3(16, 4), 128>>>(hidden, attnW);
    // 2) softmax attention -> attn_weights + x (warp-parallel scores)
    attn_kernel<<<BB, 256>>>(enc, tok, emb, out_attn);
    // 3) GRU gate GEMMs (tf32 cp.async, R13-proven), K-split by z
    gemm_gru<<<dim3(4, 24, 2), 128>>>(p_x, hidden, W_ih, W_hh, b_ih, b_hh);
    // 4) gates -> h_new (vectorized float4)
    gate_kernel<<<(BB * HH) / 1024, 256>>>(hidden, out_h);
    // 5) logits: fp16 mma (BM=256), B frags via ldmatrix, fused lse partials
    gemm_logits_f16<<<NBX, 512, 67584>>>(out_W, out_b, out_logits);
    // 6) finish log_softmax
    reduce_lse<<<BB, 128>>>();
    sub_kernel<<<dim3((VV + 255) / 256, BB), 256>>>(out_logits);
}